// round 15
// baseline (speedup 1.0000x reference)
#include <cuda_runtime.h>
#include <cuda_fp16.h>
#include <cstdint>

#define K_DIM 1024
#define O_DIM 1024
#define FP8_MAX_F 448.0f
#define AMAX_BLOCKS 1184

// ---- GEMM tiling (HMMA mma.sync path; tcgen05 unavailable at compute_103) ----
#define BM 128
#define BN 128
#define BK 64                  // 128 bytes/row fp16 = one SW128 atom
#define NT (K_DIM / BK)        // 16

// smem layout (per CTA): A fp16 2 stages | B fp16 3 stages | S fp32 A staging
#define A_STAGE   16384
#define B_OFF     32768
#define S_OFF     81920
#define SMEM_TOTAL 114688      // 112 KB; x2 CTAs = 224 KB <= 228 KB/SM

static __device__ __forceinline__ uint32_t sw128(uint32_t off) {
    return off ^ ((off >> 3) & 0x70);
}
static __device__ __forceinline__ uint32_t smem_u32(const void* p) {
    uint32_t a;
    asm("{ .reg .u64 t; cvta.to.shared.u64 t, %1; cvt.u32.u64 %0, t; }" : "=r"(a) : "l"(p));
    return a;
}

// ---- scratch (static device globals; no runtime allocation) ----
__device__ float  g_partial[AMAX_BLOCKS];   // per-block amax partials (overwritten each launch)
__device__ float  g_wscale[O_DIM];
__device__ __half g_wq[(size_t)O_DIM * K_DIM];

// ---------------- kernel 1: fused weight-quant + x-amax partials ----------------
__global__ void prep_kernel(const float* __restrict__ x, const float* __restrict__ w, int n4) {
    const int tid = threadIdx.x;
    if (blockIdx.x < O_DIM) {
        const int row = blockIdx.x;
        const float* wr = w + (size_t)row * K_DIM;
        float m = 0.f;
        for (int k = tid; k < K_DIM; k += 256) m = fmaxf(m, fabsf(wr[k]));
        #pragma unroll
        for (int o = 16; o; o >>= 1) m = fmaxf(m, __shfl_xor_sync(0xffffffffu, m, o));
        __shared__ float sm[8];
        if ((tid & 31) == 0) sm[tid >> 5] = m;
        __syncthreads();
        float am = sm[0];
        #pragma unroll
        for (int i = 1; i < 8; i++) am = fmaxf(am, sm[i]);
        float scale = fmaxf(__fdiv_rn(am, FP8_MAX_F), 1e-12f);
        if (tid == 0) g_wscale[row] = scale;
        for (int k = tid; k < K_DIM; k += 256) {
            float q = rintf(fminf(fmaxf(__fdiv_rn(wr[k], scale), -FP8_MAX_F), FP8_MAX_F));
            g_wq[(size_t)row * K_DIM + k] = __float2half_rn(q);  // exact (integer <= 448)
        }
    } else {
        const int b = blockIdx.x - O_DIM;
        const float4* x4 = (const float4*)x;
        float m = 0.f;
        const int stride = AMAX_BLOCKS * 256;
        for (int j = b * 256 + tid; j < n4; j += stride) {
            float4 v = x4[j];
            m = fmaxf(m, fmaxf(fmaxf(fabsf(v.x), fabsf(v.y)), fmaxf(fabsf(v.z), fabsf(v.w))));
        }
        #pragma unroll
        for (int o = 16; o; o >>= 1) m = fmaxf(m, __shfl_xor_sync(0xffffffffu, m, o));
        __shared__ float sm2[8];
        if ((tid & 31) == 0) sm2[tid >> 5] = m;
        __syncthreads();
        if (tid == 0) {
            float am = sm2[0];
            #pragma unroll
            for (int i = 1; i < 8; i++) am = fmaxf(am, sm2[i]);
            g_partial[b] = am;
        }
    }
}

// ---------------- kernel 2: GEMM with fused A-quantization ----------------
// A path: cp.async fp32 x -> S; per-thread convert (scale/clamp/rint) -> swizzled fp16 A stage.
// out[t, o] = acc(t,o) * (scale * wscale[o]) + bias[o]
__global__ void __launch_bounds__(256, 2)
gemm_kernel(const float* __restrict__ x, const float* __restrict__ bias, float* __restrict__ out) {
    extern __shared__ __align__(1024) char smem[];
    const uint32_t smem_base = smem_u32(smem);

    const int tid  = threadIdx.x;
    const int wid  = tid >> 5, lane = tid & 31;
    const int wm   = wid >> 2, wn = wid & 3;      // 2x4 warp grid; warp tile 64x32
    const int g    = lane >> 2, t4 = lane & 3;
    const int bm   = blockIdx.y * BM;
    const int bn   = blockIdx.x * BN;

    const float*  Axg = x + (size_t)(bm + 16 * wid) * K_DIM;  // this warp's 16 A rows
    const __half* Bg  = g_wq + (size_t)bn * K_DIM;

    // ---- B tile loader (fp16, cp.async, 3-stage) ----
#define LOAD_B(kt, s) do {                                                             \
    uint32_t sb = smem_base + B_OFF + (s) * 16384;                                     \
    _Pragma("unroll")                                                                  \
    for (int i = 0; i < 4; i++) {                                                      \
        int idx = tid + i * 256;                                                       \
        int r = idx >> 3, c = idx & 7;                                                 \
        const __half* gb = Bg + (size_t)r * K_DIM + (kt) * BK + c * 8;                 \
        uint32_t sa = sb + sw128((uint32_t)(r * 128 + c * 16));                        \
        asm volatile("cp.async.cg.shared.global [%0], [%1], 16;" :: "r"(sa), "l"(gb)); \
    }                                                                                  \
} while (0)

    // ---- A fp32 staging loader: thread's own 8x16B region of S ----
#define LOAD_A32(kt) do {                                                              \
    _Pragma("unroll")                                                                  \
    for (int i = 0; i < 8; i++) {                                                      \
        uint32_t u = (uint32_t)lane + i * 32;                                          \
        const float* ga = Axg + (u >> 4) * K_DIM + (kt) * BK + (u & 15) * 4;           \
        uint32_t sa = smem_base + S_OFF + wid * 4096 + u * 16;                         \
        asm volatile("cp.async.cg.shared.global [%0], [%1], 16;" :: "r"(sa), "l"(ga)); \
    }                                                                                  \
} while (0)

#define COMMIT() asm volatile("cp.async.commit_group;" ::: "memory")

    // ---- convert S (fp32) -> fp16 A stage `ds` (0/1); identical numerics to old xq ----
#define CONVERT(ds) do {                                                               \
    uint32_t sbase = smem_base + S_OFF + wid * 4096;                                   \
    uint32_t abase = smem_base + (ds) * A_STAGE;                                       \
    _Pragma("unroll")                                                                  \
    for (int i = 0; i < 8; i++) {                                                      \
        uint32_t u = (uint32_t)lane + i * 32;                                          \
        float f0, f1, f2, f3;                                                          \
        asm volatile("ld.shared.v4.f32 {%0,%1,%2,%3}, [%4];"                           \
                     : "=f"(f0), "=f"(f1), "=f"(f2), "=f"(f3) : "r"(sbase + u * 16));  \
        float a0 = rintf(fminf(fmaxf(f0 * inv, -FP8_MAX_F), FP8_MAX_F));               \
        float a1 = rintf(fminf(fmaxf(f1 * inv, -FP8_MAX_F), FP8_MAX_F));               \
        float a2 = rintf(fminf(fmaxf(f2 * inv, -FP8_MAX_F), FP8_MAX_F));               \
        float a3 = rintf(fminf(fmaxf(f3 * inv, -FP8_MAX_F), FP8_MAX_F));               \
        __half2 h0 = __floats2half2_rn(a0, a1);                                        \
        __half2 h1 = __floats2half2_rn(a2, a3);                                        \
        uint32_t off = (16 * wid + (u >> 4)) * 128 + (u & 15) * 8;                     \
        asm volatile("st.shared.v2.b32 [%0], {%1,%2};"                                 \
                     :: "r"(abase + sw128(off)),                                       \
                        "r"(*(uint32_t*)&h0), "r"(*(uint32_t*)&h1));                   \
    }                                                                                  \
} while (0)

    // ldmatrix per-lane constants
    const int rl = (lane & 7) + ((lane >> 3) & 1) * 8;   // row offset 0..15
    const uint32_t cl = (lane >> 4) * 16;                // +16 bytes for upper 8-lane group

    uint32_t rowA[4], xmA[4], rowB[2], xmB[2];
    #pragma unroll
    for (int im = 0; im < 4; im++) {
        rowA[im] = (uint32_t)(wm * 64 + im * 16 + rl) * 128;
        xmA[im]  = (rowA[im] >> 3) & 0x70;
    }
    #pragma unroll
    for (int in2 = 0; in2 < 2; in2++) {
        rowB[in2] = (uint32_t)(wn * 32 + in2 * 16 + rl) * 128;
        xmB[in2]  = (rowB[in2] >> 3) & 0x70;
    }

    float acc[4][4][4];
    #pragma unroll
    for (int i = 0; i < 4; i++)
        #pragma unroll
        for (int j = 0; j < 4; j++)
            #pragma unroll
            for (int r = 0; r < 4; r++) acc[i][j][r] = 0.f;

    // ---- prologue: start DMA, then reduce amax partials while it flies ----
    LOAD_B(0, 0); LOAD_A32(0); COMMIT();
    LOAD_B(1, 1); COMMIT();

    __shared__ float sred[8];
    __shared__ float s_scale, s_inv;
    {
        float m = 0.f;
        #pragma unroll 5
        for (int i = tid; i < AMAX_BLOCKS; i += 256) m = fmaxf(m, g_partial[i]);
        #pragma unroll
        for (int o = 16; o; o >>= 1) m = fmaxf(m, __shfl_xor_sync(0xffffffffu, m, o));
        if ((tid & 31) == 0) sred[tid >> 5] = m;
        __syncthreads();
        if (tid == 0) {
            float am = sred[0];
            #pragma unroll
            for (int i = 1; i < 8; i++) am = fmaxf(am, sred[i]);
            float scale = fmaxf(__fdiv_rn(am, FP8_MAX_F), 1e-12f);
            s_scale = scale;
            s_inv = __fdiv_rn(1.0f, scale);
        }
    }

    asm volatile("cp.async.wait_group 0;" ::: "memory");
    __syncthreads();                       // publishes s_inv + S(0) + B0/B1
    const float inv = s_inv;

    CONVERT(0);                            // A(0) -> Astage[0]
    LOAD_A32(1); COMMIT();                 // refill S with A32(1)

    for (int kt = 0; kt < NT; kt++) {
        asm volatile("cp.async.wait_group 0;" ::: "memory");
        // Single barrier per tile: proves compute(kt-1) done everywhere, so
        // Astage[(kt+1)&1] and Bstage[(kt+2)%3] are reusable, and cp.async data visible.
        __syncthreads();

        if (kt + 1 < NT) CONVERT((kt + 1) & 1);
        if (kt + 2 < NT) { LOAD_B(kt + 2, (kt + 2) % 3); LOAD_A32(kt + 2); COMMIT(); }

        const uint32_t stageA = smem_base + (kt & 1) * A_STAGE;
        const uint32_t stageB = smem_base + B_OFF + (kt % 3) * 16384;
        #pragma unroll
        for (int kk8 = 0; kk8 < 4; kk8++) {           // k = kk8*16
            const uint32_t colb = (uint32_t)kk8 * 32 + cl;
            uint32_t a[4][4], bf[2][4];
            #pragma unroll
            for (int im = 0; im < 4; im++) {
                uint32_t ad = stageA + rowA[im] + (colb ^ xmA[im]);
                asm volatile("ldmatrix.sync.aligned.m8n8.x4.shared.b16 {%0,%1,%2,%3}, [%4];"
                             : "=r"(a[im][0]), "=r"(a[im][1]), "=r"(a[im][2]), "=r"(a[im][3])
                             : "r"(ad));
            }
            #pragma unroll
            for (int in2 = 0; in2 < 2; in2++) {
                uint32_t ad = stageB + rowB[in2] + (colb ^ xmB[in2]);
                asm volatile("ldmatrix.sync.aligned.m8n8.x4.shared.b16 {%0,%1,%2,%3}, [%4];"
                             : "=r"(bf[in2][0]), "=r"(bf[in2][1]), "=r"(bf[in2][2]), "=r"(bf[in2][3])
                             : "r"(ad));
            }
            #pragma unroll
            for (int im = 0; im < 4; im++) {
                #pragma unroll
                for (int in_ = 0; in_ < 4; in_++) {
                    uint32_t b0 = (in_ & 1) ? bf[in_ >> 1][1] : bf[in_ >> 1][0];
                    uint32_t b1 = (in_ & 1) ? bf[in_ >> 1][3] : bf[in_ >> 1][2];
                    float* c = acc[im][in_];
                    asm volatile(
                        "mma.sync.aligned.m16n8k16.row.col.f32.f16.f16.f32 "
                        "{%0,%1,%2,%3}, {%4,%5,%6,%7}, {%8,%9}, {%0,%1,%2,%3};\n"
                        : "+f"(c[0]), "+f"(c[1]), "+f"(c[2]), "+f"(c[3])
                        : "r"(a[im][0]), "r"(a[im][1]), "r"(a[im][2]), "r"(a[im][3]),
                          "r"(b0), "r"(b1));
                }
            }
        }
    }
#undef LOAD_B
#undef LOAD_A32
#undef COMMIT
#undef CONVERT

    // epilogue: dequant + bias; streaming stores (out never re-read)
    const float iscale = s_scale;
    #pragma unroll
    for (int in_ = 0; in_ < 4; in_++) {
        int col = bn + wn * 32 + in_ * 8 + t4 * 2;
        float s0 = iscale * g_wscale[col];
        float s1 = iscale * g_wscale[col + 1];
        float b0 = bias[col];
        float b1 = bias[col + 1];
        #pragma unroll
        for (int im = 0; im < 4; im++) {
            int row = bm + wm * 64 + im * 16 + g;
            float* c = acc[im][in_];
            float2 v0 = make_float2(c[0] * s0 + b0, c[1] * s1 + b1);
            float2 v1 = make_float2(c[2] * s0 + b0, c[3] * s1 + b1);
            __stcs((float2*)&out[(size_t)row * O_DIM + col],       v0);
            __stcs((float2*)&out[(size_t)(row + 8) * O_DIM + col], v1);
        }
    }
}

// ---------------- launch ----------------
extern "C" void kernel_launch(void* const* d_in, const int* in_sizes, int n_in,
                              void* d_out, int out_size) {
    const float* x    = (const float*)d_in[0];   // [T, 1024]
    const float* w    = (const float*)d_in[1];   // [1024, 1024]
    const float* bias = (const float*)d_in[2];   // [1024]
    float* out = (float*)d_out;                  // [T, 1024] fp32

    const int n  = in_sizes[0];
    const int n4 = n / 4;
    const int T  = n / K_DIM;                    // 32768

    prep_kernel<<<O_DIM + AMAX_BLOCKS, 256>>>(x, w, n4);

    cudaFuncSetAttribute(gemm_kernel,
                         cudaFuncAttributeMaxDynamicSharedMemorySize, SMEM_TOTAL);
    dim3 grid(O_DIM / BN, T / BM);               // (8, 256)
    gemm_kernel<<<grid, 256, SMEM_TOTAL>>>(x, bias, out);
}